// round 5
// baseline (speedup 1.0000x reference)
#include <cuda_runtime.h>
#include <cstdint>

#define NC      32
#define NSTEPS  32
#define DDIM    30
#define BLOCK   256
#define MBINS   16384        // 2^14 bins
#define NT      8            // fast path specialized for 8 thetas
#define EPB     32           // edges (bins) per setup block

// Interleaved table: g_tab[bin][theta] = (A,B); A==NaN => impure bin.
__device__ float2 g_tab[MBINS * NT];

// ---------------------------------------------------------------------------
// Build the 32 per-cell step transforms for all NT thetas into s0/s1
// (layout s0[t*32+c]). Requires blockDim.x >= NT*NC = 256.
// ---------------------------------------------------------------------------
__device__ __forceinline__ void build_tables8(const float* __restrict__ theta,
                                              const float* __restrict__ basis,
                                              int tid, float* s0, float* s1)
{
    if (tid < NT * NC) {
        const int t = tid >> 5;
        const int c = tid & 31;
        const float dT = 1.0f / (float)NSTEPS;
        const float* __restrict__ ba = basis + (2 * c)     * DDIM;
        const float* __restrict__ bb = basis + (2 * c + 1) * DDIM;
        const float* __restrict__ th = theta + t * DDIM;
        float a = 0.0f, b = 0.0f;
        #pragma unroll
        for (int j = 0; j < DDIM; ++j) {
            float tj = th[j];
            a = fmaf(ba[j], tj, a);
            b = fmaf(bb[j], tj, b);
        }
        a *= dT;
        b *= dT;
        float ea  = expf(a);
        float phi = (fabsf(a) < 1e-6f) ? (1.0f + 0.5f * a) : (expm1f(a) / a);
        s0[tid] = ea;
        s1[tid] = b * phi;
    }
}

__device__ __forceinline__ int step_cell(float x)
{
    float xc = fminf(fmaxf(x * (float)NC, 0.0f), (float)(NC - 1));
    return (int)xc;   // xc >= 0 -> trunc == floor
}

__device__ __forceinline__ float2 trace_edge(int e, int t,
                                             const float* s0, const float* s1)
{
    float x = (float)e * (1.0f / (float)MBINS);   // exact in fp32
    float A = 1.0f, B = 0.0f;
    #pragma unroll
    for (int s = 0; s < NSTEPS; ++s) {
        int c = step_cell(x);
        float t0 = s0[t * 32 + c];
        float t1 = s1[t * 32 + c];
        x = fmaf(t0, x, t1);
        A = A * t0;
        B = fmaf(t0, B, t1);
    }
    return make_float2(A, B);
}

// ---------------------------------------------------------------------------
// Setup: one block per 32 bins; trace 33 edges x 8 thetas, classify by
// bitwise (A,B) equality of adjacent edges, write interleaved table.
// ---------------------------------------------------------------------------
__global__ __launch_bounds__(BLOCK)
void setup8_kernel(const float* __restrict__ theta,
                   const float* __restrict__ basis)
{
    __shared__ float s0[NT * NC], s1[NT * NC];
    __shared__ float sA[(EPB + 1) * NT], sB[(EPB + 1) * NT];

    const int tid = threadIdx.x;
    const int b   = blockIdx.x;

    build_tables8(theta, basis, tid, s0, s1);
    __syncthreads();

    const int t  = tid & (NT - 1);
    const int el = tid >> 3;              // 0..31

    float2 r = trace_edge(b * EPB + el, t, s0, s1);
    sA[el * NT + t] = r.x;
    sB[el * NT + t] = r.y;
    if (tid < NT) {                        // threads 0..7 also trace edge 32
        float2 r2 = trace_edge(b * EPB + EPB, tid, s0, s1);
        sA[EPB * NT + tid] = r2.x;
        sB[EPB * NT + tid] = r2.y;
    }
    __syncthreads();

    bool pure =
        (__float_as_int(sA[el * NT + t]) == __float_as_int(sA[(el + 1) * NT + t])) &&
        (__float_as_int(sB[el * NT + t]) == __float_as_int(sB[(el + 1) * NT + t]));

    g_tab[(b * EPB + el) * NT + t] =
        pure ? make_float2(sA[el * NT + t], sB[el * NT + t])
             : make_float2(__int_as_float(0x7FC00000), 0.0f);
}

// ---------------------------------------------------------------------------
// Main: 2 points/thread x 8 thetas. 8 batched LDG.128 fetch all results;
// impure (point,theta) pairs compacted and iterated exactly.
// ---------------------------------------------------------------------------
__global__ __launch_bounds__(BLOCK)
void main8_kernel(const float* __restrict__ points,
                  const float* __restrict__ theta,
                  const float* __restrict__ basis,
                  float* __restrict__ out,
                  int n_points)
{
    __shared__ float s0[NT * NC], s1[NT * NC];
    __shared__ int   s_list[2 * BLOCK];     // one entry max per (thread,point)
    __shared__ int   s_cnt;

    const int tid  = threadIdx.x;
    const int lane = tid & 31;

    if (tid == 0) s_cnt = 0;
    build_tables8(theta, basis, tid, s0, s1);
    __syncthreads();

    const int idx0 = blockIdx.x * (2 * BLOCK) + tid;
    const int idx1 = idx0 + BLOCK;
    const bool v0 = (idx0 < n_points);
    const bool v1 = (idx1 < n_points);

    float x0 = v0 ? points[idx0] : 0.0f;
    float x1 = v1 ? points[idx1] : 0.0f;

    // floor(x * 2^14): multiply by a power of two is exact in fp32.
    int u0 = min(max((int)__fmul_rz(x0, (float)MBINS), 0), MBINS - 1);
    int u1 = min(max((int)__fmul_rz(x1, (float)MBINS), 0), MBINS - 1);

    // Batch all 8 row loads (4 float4 per point) for MLP.
    const float4* __restrict__ T = (const float4*)g_tab;   // row u = T[u*2 .. u*2+1]? no: 64B row = 4 float4
    float4 L[8];
    #pragma unroll
    for (int j = 0; j < 4; ++j) L[j]     = __ldg(&T[(size_t)u0 * 4 + j]);
    #pragma unroll
    for (int j = 0; j < 4; ++j) L[4 + j] = __ldg(&T[(size_t)u1 * 4 + j]);

    #pragma unroll
    for (int p = 0; p < 2; ++p) {
        const int   idx   = p ? idx1 : idx0;
        const bool  valid = p ? v1 : v0;
        const float x     = p ? x1 : x0;
        int mask = 0;
        #pragma unroll
        for (int t = 0; t < NT; ++t) {
            float4 q = L[p * 4 + (t >> 1)];
            float A = (t & 1) ? q.z : q.x;
            float B = (t & 1) ? q.w : q.y;
            if (A == A) {
                if (valid) out[(size_t)t * n_points + idx] = fmaf(A, x, B);
            } else {
                mask |= 1 << t;
            }
        }
        bool slow = valid && (mask != 0);
        unsigned m = __ballot_sync(0xFFFFFFFFu, slow);
        if (m) {
            int leader = __ffs(m) - 1;
            int wbase  = 0;
            if (lane == leader) wbase = atomicAdd(&s_cnt, __popc(m));
            wbase = __shfl_sync(0xFFFFFFFFu, wbase, leader);
            if (slow)
                s_list[wbase + __popc(m & ((1u << lane) - 1u))] = (idx << 8) | mask;
        }
    }
    __syncthreads();

    // Slow path: exact reference iteration for impure (point,theta) pairs.
    const int n_imp = s_cnt;
    for (int e = tid; e < n_imp; e += BLOCK) {
        int code = s_list[e];
        int idx  = code >> 8;
        int mask = code & 0xFF;
        float x  = points[idx];
        while (mask) {
            int t = __ffs(mask) - 1;
            mask &= mask - 1;
            float xx = x;
            #pragma unroll
            for (int s = 0; s < NSTEPS; ++s) {
                int c = step_cell(xx);
                xx = fmaf(s0[t * 32 + c], xx, s1[t * 32 + c]);
            }
            out[(size_t)t * n_points + idx] = xx;
        }
    }
}

// ---------------------------------------------------------------------------
// Generic fallback (any n_theta): direct iteration, R2-style.
// ---------------------------------------------------------------------------
__global__ __launch_bounds__(BLOCK)
void generic_kernel(const float* __restrict__ points,
                    const float* __restrict__ theta,
                    const float* __restrict__ basis,
                    float* __restrict__ out,
                    int n_points)
{
    __shared__ float s0[NC], s1[NC];
    const int t   = blockIdx.y;
    const int tid = threadIdx.x;

    if (tid < NC) {
        const float dT = 1.0f / (float)NSTEPS;
        const float* ba = basis + (2 * tid)     * DDIM;
        const float* bb = basis + (2 * tid + 1) * DDIM;
        const float* th = theta + t * DDIM;
        float a = 0.0f, b = 0.0f;
        for (int j = 0; j < DDIM; ++j) {
            a = fmaf(ba[j], th[j], a);
            b = fmaf(bb[j], th[j], b);
        }
        a *= dT; b *= dT;
        float ea  = expf(a);
        float phi = (fabsf(a) < 1e-6f) ? (1.0f + 0.5f * a) : (expm1f(a) / a);
        s0[tid] = ea; s1[tid] = b * phi;
    }
    __syncthreads();

    int idx = blockIdx.x * BLOCK + tid;
    if (idx < n_points) {
        float x = points[idx];
        #pragma unroll
        for (int s = 0; s < NSTEPS; ++s) {
            int c = step_cell(x);
            x = fmaf(s0[c], x, s1[c]);
        }
        out[(size_t)t * n_points + idx] = x;
    }
}

extern "C" void kernel_launch(void* const* d_in, const int* in_sizes, int n_in,
                              void* d_out, int out_size)
{
    const float* points = (const float*)d_in[0];  // [1, n_points]
    const float* theta  = (const float*)d_in[1];  // [n_theta, 30]
    const float* basis  = (const float*)d_in[2];  // [64, 30]
    float* out = (float*)d_out;                   // [n_theta, 1, n_points]

    const int n_points = in_sizes[0];
    const int n_theta  = in_sizes[1] / DDIM;

    if (n_theta == NT) {
        setup8_kernel<<<MBINS / EPB, BLOCK>>>(theta, basis);
        int blocks = (n_points + 2 * BLOCK - 1) / (2 * BLOCK);
        main8_kernel<<<blocks, BLOCK>>>(points, theta, basis, out, n_points);
    } else {
        dim3 grid((n_points + BLOCK - 1) / BLOCK, n_theta);
        generic_kernel<<<grid, BLOCK>>>(points, theta, basis, out, n_points);
    }
}

// round 6
// speedup vs baseline: 1.7062x; 1.7062x over previous
#include <cuda_runtime.h>
#include <cstdint>

#define NC       32
#define NSTEPS   32
#define DDIM     30
#define BLOCK    256
#define PPT      8     // points per thread (independent chains for ILP)

// float2 table: tab[cell][lane] = (T00, T01). Entry 8B, lane stride 8B,
// cell stride 256B, table 8KB. Address = base8K | cell<<8 | lane<<3.
#define TAB_BYTES   (NC * 32 * 8)     // 8192
#define SLACK_FLTS  2048              // 8KB slack for runtime 8192-alignment

__global__ __launch_bounds__(BLOCK)
void cpab_kernel(const float* __restrict__ points,
                 const float* __restrict__ theta,
                 const float* __restrict__ basis,
                 float* __restrict__ out,
                 int n_points)
{
    __shared__ float sbuf[TAB_BYTES / 4 + SLACK_FLTS];
    __shared__ float s0[NC];
    __shared__ float s1[NC];

    const int t    = blockIdx.y;
    const int tid  = threadIdx.x;
    const int lane = tid & 31;

    // Runtime 8192-aligned table base in shared address space.
    uint32_t sbase = (uint32_t)__cvta_generic_to_shared(sbuf);
    uint32_t abase = (sbase + 8191u) & ~8191u;
    // Per-thread constant: base | lane*8. Lane bits [7:3] disjoint from the
    // cell field (bits [12:8]) and from the aligned base (bits >= 13).
    uint32_t C = abase | ((uint32_t)lane << 3);

    // --- 32 per-cell step transforms for this theta ---
    if (tid < NC) {
        const float dT = 1.0f / (float)NSTEPS;
        const float* __restrict__ ba = basis + (2 * tid)     * DDIM;
        const float* __restrict__ bb = basis + (2 * tid + 1) * DDIM;
        const float* __restrict__ th = theta + t * DDIM;
        float a = 0.0f, b = 0.0f;
        #pragma unroll
        for (int j = 0; j < DDIM; ++j) {
            float tj = th[j];
            a = fmaf(ba[j], tj, a);
            b = fmaf(bb[j], tj, b);
        }
        a *= dT;
        b *= dT;
        float ea  = expf(a);
        float phi = (fabsf(a) < 1e-6f) ? (1.0f + 0.5f * a) : (expm1f(a) / a);
        s0[tid] = ea;
        s1[tid] = b * phi;
    }
    __syncthreads();

    // Replicate into the lane-exclusive float2 layout (conflict-free gather).
    {
        float2* tab = (float2*)(sbuf + ((abase - sbase) >> 2));
        #pragma unroll
        for (int i = tid; i < NC * 32; i += BLOCK) {
            int cell = i >> 5;
            tab[i] = make_float2(s0[cell], s1[cell]);
        }
    }
    __syncthreads();

    // --- Main integration: 8 independent chains per thread ---
    const int base = blockIdx.x * (BLOCK * PPT) + tid;

    float x[PPT];
    #pragma unroll
    for (int k = 0; k < PPT; ++k) {
        int idx = base + k * BLOCK;
        x[k] = (idx < n_points) ? points[idx] : 0.0f;
    }

    #pragma unroll 4
    for (int s = 0; s < NSTEPS; ++s) {
        #pragma unroll
        for (int k = 0; k < PPT; ++k) {
            // bits = 0x4B000000 + floor(x*8192), exact (RZ fma, |x*8192| < 2^23)
            int bi = (int)__float_as_uint(__fmaf_rz(x[k], 8192.0f, 8388608.0f));
            bi = max(bi, 0x4B000000);          // x < 0  -> cell 0
            bi = min(bi, 0x4B001FFF);          // x >= 1 -> cell 31
            // addr = base | lane*8 | cell*256  (single LOP3)
            uint32_t addr = ((uint32_t)bi & 0x1F00u) | C;
            float t0, t1;
            asm volatile("ld.shared.v2.f32 {%0,%1}, [%2];"
                         : "=f"(t0), "=f"(t1) : "r"(addr));
            x[k] = fmaf(t0, x[k], t1);
        }
    }

    float* __restrict__ o = out + (size_t)t * (size_t)n_points;
    #pragma unroll
    for (int k = 0; k < PPT; ++k) {
        int idx = base + k * BLOCK;
        if (idx < n_points) o[idx] = x[k];
    }
}

extern "C" void kernel_launch(void* const* d_in, const int* in_sizes, int n_in,
                              void* d_out, int out_size)
{
    const float* points = (const float*)d_in[0];  // [1, n_points]
    const float* theta  = (const float*)d_in[1];  // [n_theta, 30]
    const float* basis  = (const float*)d_in[2];  // [64, 30]
    float* out = (float*)d_out;                   // [n_theta, 1, n_points]

    const int n_points = in_sizes[0];
    const int n_theta  = in_sizes[1] / DDIM;

    dim3 grid((n_points + BLOCK * PPT - 1) / (BLOCK * PPT), n_theta);
    cpab_kernel<<<grid, BLOCK>>>(points, theta, basis, out, n_points);
}